// round 7
// baseline (speedup 1.0000x reference)
#include <cuda_runtime.h>
#include <cuda_fp16.h>
#include <math.h>
#include <stdint.h>

#define CIN   64
#define COUT  64
#define HH    112
#define WW    112
#define NB    32
#define HW    (HH*WW)            // 12544
#define TOTAL (NB*COUT*HW)       // 25690112
#define MCNT  (NB*HW)            // 401408

// conv tiling: block = 64 co x 256 px (16x16), 4 warps each m64xn64, fp16 mma k16
#define TPX 16
#define TPY 16
#define NPOS (18*18)             // 324 halo positions
#define ASTR 72                  // halves per pos row: LDSM conflict-free
#define WSTR 72
#define S_ACT_HALVES (NPOS*ASTR)          // 23328
#define S_W_HALVES   (64*WSTR)            // 4608 per buffer (x2)
#define SMEM_BYTES ((S_ACT_HALVES + 2*S_W_HALVES)*2)   // 65088 B

// ---------------- device scratch ----------------
__device__ float  g_t1[TOTAL];
__device__ float  g_t2[TOTAL];
__device__ __half g_w1[9*64*64];   // [tap][co][ci]
__device__ __half g_w2[9*64*64];
__device__ float  g_sum[2][COUT];
__device__ float  g_sq[2][COUT];
__device__ float  g_scale[2][COUT];
__device__ float  g_bias[2][COUT];

__device__ __forceinline__ void mma16(float* d, const uint32_t* a, uint32_t b0, uint32_t b1) {
    asm volatile(
        "mma.sync.aligned.m16n8k16.row.col.f32.f16.f16.f32 "
        "{%0,%1,%2,%3}, {%4,%5,%6,%7}, {%8,%9}, {%0,%1,%2,%3};\n"
        : "+f"(d[0]), "+f"(d[1]), "+f"(d[2]), "+f"(d[3])
        : "r"(a[0]), "r"(a[1]), "r"(a[2]), "r"(a[3]), "r"(b0), "r"(b1));
}
__device__ __forceinline__ void ldsm4(uint32_t& r0, uint32_t& r1, uint32_t& r2, uint32_t& r3,
                                      uint32_t addr) {
    asm volatile("ldmatrix.sync.aligned.m8n8.x4.shared.b16 {%0,%1,%2,%3}, [%4];"
        : "=r"(r0), "=r"(r1), "=r"(r2), "=r"(r3) : "r"(addr));
}

// ---------------- prep: ternarize + repack(half) + zero stats ----------------
__global__ void prep_kernel(const float* __restrict__ w1,
                            const float* __restrict__ w2) {
    int idx = blockIdx.x * 256 + threadIdx.x;
    if (idx < COUT) {
        g_sum[0][idx] = 0.f; g_sum[1][idx] = 0.f;
        g_sq[0][idx]  = 0.f; g_sq[1][idx]  = 0.f;
    }
    if (idx < 9*64*64) {
        // src OIHW: idx = (co*64 + ci)*9 + t
        int co = idx / (64*9);
        int ci = (idx / 9) & 63;
        int t  = idx % 9;
        int dst = t*4096 + co*64 + ci;
        float a = w1[idx];
        g_w1[dst] = __float2half((fabsf(a) > 0.3f) ? (a > 0.f ? 1.f : -1.f) : 0.f);
        float b = w2[idx];
        g_w2[dst] = __float2half((fabsf(b) > 0.3f) ? (b > 0.f ? 1.f : -1.f) : 0.f);
    }
}

// ---------------- conv3x3 via 9 shifted 1x1 GEMMs, fp16 mma + ldmatrix ----
// 4 warps, each computes m64 (all co) x n64 px: B fragments loaded exactly once.
// PASS 1: in=x, out=g_t1.  PASS 2: in=BN1+hardtanh(g_t1), out=g_t2 + x.
template<int PASS>
__global__ void __launch_bounds__(128, 2) conv_mma_kernel(const float* __restrict__ x) {
    extern __shared__ __half smem_h[];
    __half* s_act = smem_h;                       // [pos][ci] stride 72
    __half* s_wb  = smem_h + S_ACT_HALVES;        // 2 weight buffers [co][ci] stride 72
    __shared__ float s_s[COUT], s_b[COUT];
    __shared__ float s_sum[COUT], s_sq[COUT];

    const float*  in   = (PASS == 1) ? x    : g_t1;
    const __half* wrep = (PASS == 1) ? g_w1 : g_w2;
    float*        out  = (PASS == 1) ? g_t1 : g_t2;

    const int tid  = threadIdx.x;
    const int lane = tid & 31;
    const int wn   = tid >> 5;       // 4 n-warps, each 64 px, all 64 co
    const int q    = lane & 3;
    const int nidx = lane >> 2;
    const int w0   = blockIdx.x * TPX;
    const int h0   = blockIdx.y * TPY;
    const int n    = blockIdx.z;

    if (tid < COUT) {
        s_sum[tid] = 0.f; s_sq[tid] = 0.f;
        if (PASS == 2) { s_s[tid] = g_scale[0][tid]; s_b[tid] = g_bias[0][tid]; }
    }
    __syncthreads();

    // prefetch tap-0 weights (4 x float4 = 32 halves / thread, 128 threads)
    float4 wpf[4];
#pragma unroll
    for (int k = 0; k < 4; k++)
        wpf[k] = reinterpret_cast<const float4*>(wrep)[tid + k*128];

    // ---- stage activation tile: 64 ci x 18x18 halo, fp16, [pos][ci] ----
    // lanes: 4 pos-workers x 8 ci-pair-workers; 4 warps stride the pos space
    {
        const int posw = (tid & 3) | (wn << 2);           // 0..15
        const int cpw  = (tid >> 2) & 7;                  // 0..7
        const int ci0  = 2*cpw;
        for (int pos = posw; pos < NPOS; pos += 16) {
            int py = pos / 18;
            int px = pos - py*18;
            int gh = h0 + py - 1, gw = w0 + px - 1;
            bool valid = ((unsigned)gh < (unsigned)HH) && ((unsigned)gw < (unsigned)WW);
            const float* p0 = in + (n*64)*HW + gh*WW + gw;
            int word = pos*ASTR;
#pragma unroll
            for (int j = 0; j < 4; j++) {
                int ci = ci0 + 16*j;
                float v0 = 0.f, v1 = 0.f;
                if (valid) {
                    const float* p = p0 + ci*HW;
                    v0 = p[0];
                    v1 = p[HW];
                    if (PASS == 2) {
                        v0 = fminf(fmaxf(fmaf(v0, s_s[ci],   s_b[ci]),   -1.f), 1.f);
                        v1 = fminf(fmaxf(fmaf(v1, s_s[ci+1], s_b[ci+1]), -1.f), 1.f);
                    }
                }
                *reinterpret_cast<__half2*>(s_act + word + ci) = __floats2half2_rn(v0, v1);
            }
        }
    }

    float acc[4][8][4];
#pragma unroll
    for (int mt = 0; mt < 4; mt++)
#pragma unroll
        for (int nt = 0; nt < 8; nt++)
#pragma unroll
            for (int r = 0; r < 4; r++) acc[mt][nt][r] = 0.f;

    // ---- per-lane LDSM base addresses (byte offsets in shared space) ----
    const uint32_t sw_b = (uint32_t)__cvta_generic_to_shared(s_wb);
    const uint32_t sa_b = (uint32_t)__cvta_generic_to_shared(s_act);
    // A: lanes 0-15 rows m0-15 @k0 | 16-31 rows m0-15 @k8; mt adds 16 rows
    const uint32_t aA = sw_b + (((lane & 15)*WSTR) + (lane >> 4)*8) * 2;
    // B: lanes 0-7 n0-7 @k0 | 8-15 n0-7 @k8 | 16-23 n8-15 @k0 | 24-31 n8-15 @k8
    const int px_l  = ((lane >> 4) & 1)*8 + (lane & 7);
    const int kof_l = ((lane >> 3) & 1)*8;
    const uint32_t bB = sa_b + (((wn*4)*18 + px_l)*ASTR + kof_l) * 2;

#pragma unroll
    for (int tap = 0; tap < 9; ++tap) {
        __half* s_w = s_wb + (tap & 1)*S_W_HALVES;
        const uint32_t wbuf = (tap & 1) * (S_W_HALVES*2);
#pragma unroll
        for (int k = 0; k < 4; k++) {
            int v = tid + k*128;
            *reinterpret_cast<float4*>(s_w + (v >> 3)*WSTR + (v & 7)*8) = wpf[k];
        }
        if (tap < 8) {
            const float4* wsrc = reinterpret_cast<const float4*>(wrep + (tap+1)*4096);
#pragma unroll
            for (int k = 0; k < 4; k++) wpf[k] = wsrc[tid + k*128];
        }
        __syncthreads();   // buffer (tap&1) ready; prior reads of it finished a tap ago

        const int dy = tap / 3, dx = tap - dy*3;
        const uint32_t tapoff = (uint32_t)((dy*18 + dx)*ASTR*2);

#pragma unroll
        for (int ch = 0; ch < 4; ch++) {
            const uint32_t ko = ch*32;           // 16 halves per chunk
            uint32_t a[4][4];
#pragma unroll
            for (int mt = 0; mt < 4; mt++)
                ldsm4(a[mt][0], a[mt][1], a[mt][2], a[mt][3],
                      aA + wbuf + ko + (uint32_t)(mt*16*WSTR*2));
#pragma unroll
            for (int pr = 0; pr < 4; pr++) {
                uint32_t b0, b1, b2, b3;
                ldsm4(b0, b1, b2, b3, bB + tapoff + (uint32_t)(pr*18*ASTR*2) + ko);
#pragma unroll
                for (int mt = 0; mt < 4; mt++) {
                    mma16(acc[mt][2*pr],   a[mt], b0, b1);
                    mma16(acc[mt][2*pr+1], a[mt], b2, b3);
                }
            }
        }
    }

    // ---- epilogue: residual (+PASS2), store, fused BN stats ----
#pragma unroll
    for (int mt = 0; mt < 4; mt++) {
        int co_lo = mt*16 + nidx;
        float slo = 0.f, qlo = 0.f, shi = 0.f, qhi = 0.f;
#pragma unroll
        for (int nt = 0; nt < 8; nt++) {
            int p  = wn*64 + nt*8 + 2*q;
            int py = p >> 4, px = p & 15;
            int base = (n*64 + co_lo)*HW + (h0 + py)*WW + (w0 + px);
            float2 v0 = make_float2(acc[mt][nt][0], acc[mt][nt][1]);
            float2 v1 = make_float2(acc[mt][nt][2], acc[mt][nt][3]);
            if (PASS == 2) {
                float2 r0 = *(const float2*)(x + base);
                float2 r1 = *(const float2*)(x + base + 8*HW);
                v0.x += r0.x; v0.y += r0.y;
                v1.x += r1.x; v1.y += r1.y;
            }
            *(float2*)(out + base)        = v0;
            *(float2*)(out + base + 8*HW) = v1;
            slo += v0.x + v0.y;
            qlo += v0.x*v0.x + v0.y*v0.y;
            shi += v1.x + v1.y;
            qhi += v1.x*v1.x + v1.y*v1.y;
        }
#pragma unroll
        for (int o = 1; o <= 2; o <<= 1) {
            slo += __shfl_xor_sync(0xffffffffu, slo, o);
            qlo += __shfl_xor_sync(0xffffffffu, qlo, o);
            shi += __shfl_xor_sync(0xffffffffu, shi, o);
            qhi += __shfl_xor_sync(0xffffffffu, qhi, o);
        }
        if (q == 0) {
            atomicAdd(&s_sum[co_lo],     slo);
            atomicAdd(&s_sq[co_lo],      qlo);
            atomicAdd(&s_sum[co_lo + 8], shi);
            atomicAdd(&s_sq[co_lo + 8],  qhi);
        }
    }
    __syncthreads();
    if (tid < COUT) {
        atomicAdd(&g_sum[PASS-1][tid], s_sum[tid]);
        atomicAdd(&g_sq[PASS-1][tid],  s_sq[tid]);
    }
}

// ---------------- fold BN stats ----------------
template<int PASS>
__global__ void finalize_kernel(const float* __restrict__ g,
                                const float* __restrict__ b) {
    int c = threadIdx.x;
    if (c < COUT) {
        const float inv = 1.f / (float)MCNT;
        float mean = g_sum[PASS-1][c] * inv;
        float var  = g_sq[PASS-1][c] * inv - mean*mean;
        float s    = g[c] * rsqrtf(var + 1e-5f);
        g_scale[PASS-1][c] = s;
        g_bias[PASS-1][c]  = b[c] - mean*s;
    }
}

// ---------------- final BN2 + hardtanh ----------------
__global__ void bnact_kernel(float* __restrict__ out) {
    int i = blockIdx.x * 256 + threadIdx.x;
    if (i >= TOTAL/4) return;
    int c = (i / (HW/4)) & 63;
    float s  = g_scale[1][c];
    float bb = g_bias[1][c];
    float4 v = reinterpret_cast<const float4*>(g_t2)[i];
    v.x = fminf(fmaxf(fmaf(v.x, s, bb), -1.f), 1.f);
    v.y = fminf(fmaxf(fmaf(v.y, s, bb), -1.f), 1.f);
    v.z = fminf(fmaxf(fmaf(v.z, s, bb), -1.f), 1.f);
    v.w = fminf(fmaxf(fmaf(v.w, s, bb), -1.f), 1.f);
    reinterpret_cast<float4*>(out)[i] = v;
}

// ---------------- launch ----------------
extern "C" void kernel_launch(void* const* d_in, const int* in_sizes, int n_in,
                              void* d_out, int out_size) {
    const float* x  = (const float*)d_in[0];
    const float* w1 = (const float*)d_in[1];
    const float* g1 = (const float*)d_in[2];
    const float* b1 = (const float*)d_in[3];
    const float* w2 = (const float*)d_in[4];
    const float* g2 = (const float*)d_in[5];
    const float* b2 = (const float*)d_in[6];
    float* out = (float*)d_out;

    cudaFuncSetAttribute(conv_mma_kernel<1>,
                         cudaFuncAttributeMaxDynamicSharedMemorySize, SMEM_BYTES);
    cudaFuncSetAttribute(conv_mma_kernel<2>,
                         cudaFuncAttributeMaxDynamicSharedMemorySize, SMEM_BYTES);

    prep_kernel<<<(9*64*64 + 255)/256, 256>>>(w1, w2);

    dim3 cgrid(WW/TPX, HH/TPY, NB);   // (7, 7, 32)
    conv_mma_kernel<1><<<cgrid, 128, SMEM_BYTES>>>(x);
    finalize_kernel<1><<<1, 64>>>(g1, b1);

    conv_mma_kernel<2><<<cgrid, 128, SMEM_BYTES>>>(x);
    finalize_kernel<2><<<1, 64>>>(g2, b2);

    bnact_kernel<<<(TOTAL/4 + 255)/256, 256>>>(out);
}